// round 1
// baseline (speedup 1.0000x reference)
#include <cuda_runtime.h>

// Problem dims (fixed per reference)
#define TT 64
#define BB 1024
#define NN 512
#define M_TOTAL (TT * BB)   // 65536 rows for both GEMMs

// Scratch: h = fc1 output, s = spikes (fc2 input). __device__ globals per rules.
__device__ float g_h[(size_t)TT * BB * NN];
__device__ float g_s[(size_t)TT * BB * NN];

// ---------------------------------------------------------------------------
// Tiled fp32 GEMM (NT): C[M,N] = A[M,K] @ B[N,K]^T + bias[N]
// Block tile 128x128, K-tile 16, 256 threads, 8x8 microtile, double-buffered.
// M=65536, N=512, K=512 are exact multiples of the tiles: no bounds checks.
// ---------------------------------------------------------------------------
#define BM 128
#define BN 128
#define BK 16

__global__ __launch_bounds__(256, 2) void gemm_nt_bias(
    const float* __restrict__ A,     // [M, K] row-major
    const float* __restrict__ B,     // [N, K] row-major (weight, torch layout)
    const float* __restrict__ bias,  // [N]
    float* __restrict__ C,           // [M, N]
    int M, int N, int K)
{
    __shared__ float As[2][BK][BM + 4];
    __shared__ float Bs[2][BK][BN + 4];

    const int tid = threadIdx.x;
    const int tx = tid & 15;   // 0..15 -> N microtile
    const int ty = tid >> 4;   // 0..15 -> M microtile

    const int rowBase = blockIdx.y * BM;
    const int colBase = blockIdx.x * BN;

    const float* Ablk = A + (size_t)rowBase * K;
    const float* Bblk = B + (size_t)colBase * K;

    float acc[8][8];
#pragma unroll
    for (int i = 0; i < 8; i++)
#pragma unroll
        for (int j = 0; j < 8; j++) acc[i][j] = 0.0f;

    const int nTiles = K / BK;  // 32

    float4 aFrag[2], bFrag[2];

    // Prefetch tile 0 into registers
#pragma unroll
    for (int i = 0; i < 2; i++) {
        int l  = tid + i * 256;
        int r  = l >> 2;        // 0..127
        int c4 = l & 3;         // 0..3 (float4 within 16-wide K tile)
        aFrag[i] = *(const float4*)(Ablk + (size_t)r * K + c4 * 4);
        bFrag[i] = *(const float4*)(Bblk + (size_t)r * K + c4 * 4);
    }
    // Store tile 0 to smem buffer 0 (transposed: smem[k][row])
#pragma unroll
    for (int i = 0; i < 2; i++) {
        int l = tid + i * 256;
        int r = l >> 2;
        int c = (l & 3) * 4;
        As[0][c + 0][r] = aFrag[i].x; As[0][c + 1][r] = aFrag[i].y;
        As[0][c + 2][r] = aFrag[i].z; As[0][c + 3][r] = aFrag[i].w;
        Bs[0][c + 0][r] = bFrag[i].x; Bs[0][c + 1][r] = bFrag[i].y;
        Bs[0][c + 2][r] = bFrag[i].z; Bs[0][c + 3][r] = bFrag[i].w;
    }
    __syncthreads();

    for (int kt = 0; kt < nTiles; kt++) {
        const int cur = kt & 1;
        const int nxt = cur ^ 1;

        // Prefetch next K tile into registers (hides LDG latency behind FMAs)
        if (kt + 1 < nTiles) {
            const int k0 = (kt + 1) * BK;
#pragma unroll
            for (int i = 0; i < 2; i++) {
                int l  = tid + i * 256;
                int r  = l >> 2;
                int c4 = l & 3;
                aFrag[i] = *(const float4*)(Ablk + (size_t)r * K + k0 + c4 * 4);
                bFrag[i] = *(const float4*)(Bblk + (size_t)r * K + k0 + c4 * 4);
            }
        }

        // Compute on current smem tile
#pragma unroll
        for (int k = 0; k < BK; k++) {
            float4 a0 = *(const float4*)&As[cur][k][ty * 8];
            float4 a1 = *(const float4*)&As[cur][k][ty * 8 + 4];
            float4 b0 = *(const float4*)&Bs[cur][k][tx * 8];
            float4 b1 = *(const float4*)&Bs[cur][k][tx * 8 + 4];
            float a[8] = {a0.x, a0.y, a0.z, a0.w, a1.x, a1.y, a1.z, a1.w};
            float b[8] = {b0.x, b0.y, b0.z, b0.w, b1.x, b1.y, b1.z, b1.w};
#pragma unroll
            for (int i = 0; i < 8; i++)
#pragma unroll
                for (int j = 0; j < 8; j++)
                    acc[i][j] = fmaf(a[i], b[j], acc[i][j]);
        }

        // Commit next tile to the other smem buffer
        if (kt + 1 < nTiles) {
#pragma unroll
            for (int i = 0; i < 2; i++) {
                int l = tid + i * 256;
                int r = l >> 2;
                int c = (l & 3) * 4;
                As[nxt][c + 0][r] = aFrag[i].x; As[nxt][c + 1][r] = aFrag[i].y;
                As[nxt][c + 2][r] = aFrag[i].z; As[nxt][c + 3][r] = aFrag[i].w;
                Bs[nxt][c + 0][r] = bFrag[i].x; Bs[nxt][c + 1][r] = bFrag[i].y;
                Bs[nxt][c + 2][r] = bFrag[i].z; Bs[nxt][c + 3][r] = bFrag[i].w;
            }
        }
        __syncthreads();
    }

    // Epilogue: += bias, vectorized stores
    const float4 bv0 = *(const float4*)(bias + colBase + tx * 8);
    const float4 bv1 = *(const float4*)(bias + colBase + tx * 8 + 4);
#pragma unroll
    for (int i = 0; i < 8; i++) {
        const size_t r = (size_t)(rowBase + ty * 8 + i);
        float4 o0, o1;
        o0.x = acc[i][0] + bv0.x; o0.y = acc[i][1] + bv0.y;
        o0.z = acc[i][2] + bv0.z; o0.w = acc[i][3] + bv0.w;
        o1.x = acc[i][4] + bv1.x; o1.y = acc[i][5] + bv1.y;
        o1.z = acc[i][6] + bv1.z; o1.w = acc[i][7] + bv1.w;
        *(float4*)(C + r * N + colBase + tx * 8)     = o0;
        *(float4*)(C + r * N + colBase + tx * 8 + 4) = o1;
    }
}

// ---------------------------------------------------------------------------
// Multistep LIF over T. One thread per (b, n) element; sequential over t.
// charge: v = v + (h - v)/tau (tau=2) ; fire: spike = (v >= 1) ; hard reset.
// ---------------------------------------------------------------------------
__global__ __launch_bounds__(256) void lif_scan(
    const float* __restrict__ h, float* __restrict__ s)
{
    const int idx = blockIdx.x * blockDim.x + threadIdx.x;  // 0 .. BB*NN-1
    const size_t stride = (size_t)BB * NN;
    float v = 0.0f;
#pragma unroll 8
    for (int t = 0; t < TT; t++) {
        const float ht = h[(size_t)t * stride + idx];
        v = v + (ht - v) * 0.5f;
        const bool fire = (v >= 1.0f);
        s[(size_t)t * stride + idx] = fire ? 1.0f : 0.0f;
        v = fire ? 0.0f : v;
    }
}

// ---------------------------------------------------------------------------
// kernel_launch: fc1 GEMM -> LIF scan -> fc2 GEMM
// Inputs (metadata order): x, fc1_w, fc1_b, fc2_w, fc2_b
// ---------------------------------------------------------------------------
extern "C" void kernel_launch(void* const* d_in, const int* in_sizes, int n_in,
                              void* d_out, int out_size)
{
    const float* x     = (const float*)d_in[0];
    const float* fc1_w = (const float*)d_in[1];
    const float* fc1_b = (const float*)d_in[2];
    const float* fc2_w = (const float*)d_in[3];
    const float* fc2_b = (const float*)d_in[4];
    float* out = (float*)d_out;

    float* h = nullptr;
    float* s = nullptr;
    cudaGetSymbolAddress((void**)&h, g_h);
    cudaGetSymbolAddress((void**)&s, g_s);

    dim3 block(256);
    dim3 gridGemm(NN / BN, M_TOTAL / BM);  // (4, 512)

    // fc1: h = x @ W1^T + b1
    gemm_nt_bias<<<gridGemm, block>>>(x, fc1_w, fc1_b, h, M_TOTAL, NN, NN);

    // LIF scan over T
    lif_scan<<<(BB * NN) / 256, block>>>(h, s);

    // fc2: out = s @ W2^T + b2
    gemm_nt_bias<<<gridGemm, block>>>(s, fc2_w, fc2_b, out, M_TOTAL, NN, NN);
}

// round 9
// speedup vs baseline: 1.4635x; 1.4635x over previous
#include <cuda_runtime.h>
#include <cuda_fp16.h>
#include <cstdint>

// Problem dims (fixed)
#define TT 64
#define BB 1024
#define NN 512
#define KK 512
#define M_TOTAL (TT * BB)   // 65536

// Scratch
__device__ float  g_h[(size_t)M_TOTAL * NN];    // fc1 output (fp32)
__device__ __half g_s[(size_t)M_TOTAL * NN];    // spikes (exact in fp16)
__device__ __half g_w2h[NN * KK];
__device__ __half g_w2l[NN * KK];

// ---------------------------------------------------------------------------
// fp32 SIMT GEMM (NT): C = A @ B^T + bias  — identical to the R1 kernel
// (measured: 742 us, rel_err 0.0 for fc1). Block 128x128, BK=16, 256 thr.
// ---------------------------------------------------------------------------
#define BMF 128
#define BNF 128
#define BKF 16

__global__ __launch_bounds__(256, 2) void gemm_f32(
    const float* __restrict__ A, const float* __restrict__ B,
    const float* __restrict__ bias, float* __restrict__ C,
    int M, int N, int K)
{
    __shared__ float As[2][BKF][BMF + 4];
    __shared__ float Bs[2][BKF][BNF + 4];

    const int tid = threadIdx.x;
    const int tx = tid & 15;
    const int ty = tid >> 4;

    const int rowBase = blockIdx.y * BMF;
    const int colBase = blockIdx.x * BNF;

    const float* Ablk = A + (size_t)rowBase * K;
    const float* Bblk = B + (size_t)colBase * K;

    float acc[8][8];
#pragma unroll
    for (int i = 0; i < 8; i++)
#pragma unroll
        for (int j = 0; j < 8; j++) acc[i][j] = 0.0f;

    const int nTiles = K / BKF;
    float4 aFrag[2], bFrag[2];

#pragma unroll
    for (int i = 0; i < 2; i++) {
        int l = tid + i * 256;
        int r = l >> 2, c4 = l & 3;
        aFrag[i] = *(const float4*)(Ablk + (size_t)r * K + c4 * 4);
        bFrag[i] = *(const float4*)(Bblk + (size_t)r * K + c4 * 4);
    }
#pragma unroll
    for (int i = 0; i < 2; i++) {
        int l = tid + i * 256;
        int r = l >> 2, c = (l & 3) * 4;
        As[0][c + 0][r] = aFrag[i].x; As[0][c + 1][r] = aFrag[i].y;
        As[0][c + 2][r] = aFrag[i].z; As[0][c + 3][r] = aFrag[i].w;
        Bs[0][c + 0][r] = bFrag[i].x; Bs[0][c + 1][r] = bFrag[i].y;
        Bs[0][c + 2][r] = bFrag[i].z; Bs[0][c + 3][r] = bFrag[i].w;
    }
    __syncthreads();

    for (int kt = 0; kt < nTiles; kt++) {
        const int cur = kt & 1;
        const int nxt = cur ^ 1;

        if (kt + 1 < nTiles) {
            const int k0 = (kt + 1) * BKF;
#pragma unroll
            for (int i = 0; i < 2; i++) {
                int l = tid + i * 256;
                int r = l >> 2, c4 = l & 3;
                aFrag[i] = *(const float4*)(Ablk + (size_t)r * K + k0 + c4 * 4);
                bFrag[i] = *(const float4*)(Bblk + (size_t)r * K + k0 + c4 * 4);
            }
        }

#pragma unroll
        for (int k = 0; k < BKF; k++) {
            float4 a0 = *(const float4*)&As[cur][k][ty * 8];
            float4 a1 = *(const float4*)&As[cur][k][ty * 8 + 4];
            float4 b0 = *(const float4*)&Bs[cur][k][tx * 8];
            float4 b1 = *(const float4*)&Bs[cur][k][tx * 8 + 4];
            float a[8] = {a0.x, a0.y, a0.z, a0.w, a1.x, a1.y, a1.z, a1.w};
            float b[8] = {b0.x, b0.y, b0.z, b0.w, b1.x, b1.y, b1.z, b1.w};
#pragma unroll
            for (int i = 0; i < 8; i++)
#pragma unroll
                for (int j = 0; j < 8; j++)
                    acc[i][j] = fmaf(a[i], b[j], acc[i][j]);
        }

        if (kt + 1 < nTiles) {
#pragma unroll
            for (int i = 0; i < 2; i++) {
                int l = tid + i * 256;
                int r = l >> 2, c = (l & 3) * 4;
                As[nxt][c + 0][r] = aFrag[i].x; As[nxt][c + 1][r] = aFrag[i].y;
                As[nxt][c + 2][r] = aFrag[i].z; As[nxt][c + 3][r] = aFrag[i].w;
                Bs[nxt][c + 0][r] = bFrag[i].x; Bs[nxt][c + 1][r] = bFrag[i].y;
                Bs[nxt][c + 2][r] = bFrag[i].z; Bs[nxt][c + 3][r] = bFrag[i].w;
            }
        }
        __syncthreads();
    }

    const float4 bv0 = *(const float4*)(bias + colBase + tx * 8);
    const float4 bv1 = *(const float4*)(bias + colBase + tx * 8 + 4);
#pragma unroll
    for (int i = 0; i < 8; i++) {
        const size_t r = (size_t)(rowBase + ty * 8 + i);
        float4 o0, o1;
        o0.x = acc[i][0] + bv0.x; o0.y = acc[i][1] + bv0.y;
        o0.z = acc[i][2] + bv0.z; o0.w = acc[i][3] + bv0.w;
        o1.x = acc[i][4] + bv1.x; o1.y = acc[i][5] + bv1.y;
        o1.z = acc[i][6] + bv1.z; o1.w = acc[i][7] + bv1.w;
        *(float4*)(C + r * N + colBase + tx * 8)     = o0;
        *(float4*)(C + r * N + colBase + tx * 8 + 4) = o1;
    }
}

// ---------------------------------------------------------------------------
// mma.sync helpers (sm_80-baseline PTX; assembles for sm_103 base)
// ---------------------------------------------------------------------------
__device__ __forceinline__ uint32_t smem_u32(const void* p) {
    uint32_t a;
    asm("{ .reg .u64 t; cvta.to.shared.u64 t, %1; cvt.u32.u64 %0, t; }"
        : "=r"(a) : "l"(p));
    return a;
}
__device__ __forceinline__ void cp16(uint32_t saddr, const void* g) {
    asm volatile("cp.async.cg.shared.global [%0], [%1], 16;" :: "r"(saddr), "l"(g));
}
__device__ __forceinline__ void ldsm_x4(uint32_t* r, uint32_t a) {
    asm volatile("ldmatrix.sync.aligned.m8n8.x4.shared.b16 {%0,%1,%2,%3}, [%4];"
                 : "=r"(r[0]), "=r"(r[1]), "=r"(r[2]), "=r"(r[3]) : "r"(a));
}
__device__ __forceinline__ void mma16816(float* d, const uint32_t* a,
                                         uint32_t b0, uint32_t b1) {
    asm volatile(
        "mma.sync.aligned.m16n8k16.row.col.f32.f16.f16.f32 "
        "{%0,%1,%2,%3}, {%4,%5,%6,%7}, {%8,%9}, {%0,%1,%2,%3};"
        : "+f"(d[0]), "+f"(d[1]), "+f"(d[2]), "+f"(d[3])
        : "r"(a[0]), "r"(a[1]), "r"(a[2]), "r"(a[3]), "r"(b0), "r"(b1));
}

// Split fp32 -> fp16 hi + lo (for W2 only)
__global__ __launch_bounds__(256) void split_f32_f16(
    const float* __restrict__ x, __half* __restrict__ h, __half* __restrict__ l,
    int n4)
{
    int i = blockIdx.x * blockDim.x + threadIdx.x;
    if (i >= n4) return;
    float4 v = ((const float4*)x)[i];
    float f[4] = {v.x, v.y, v.z, v.w};
    __half hh[4], ll[4];
#pragma unroll
    for (int j = 0; j < 4; j++) {
        hh[j] = __float2half_rn(f[j]);
        ll[j] = __float2half_rn(f[j] - __half2float(hh[j]));
    }
    ((__half2*)h)[2 * i]     = __halves2half2(hh[0], hh[1]);
    ((__half2*)h)[2 * i + 1] = __halves2half2(hh[2], hh[3]);
    ((__half2*)l)[2 * i]     = __halves2half2(ll[0], ll[1]);
    ((__half2*)l)[2 * i + 1] = __halves2half2(ll[2], ll[3]);
}

// ---------------------------------------------------------------------------
// mma.sync GEMM (fc2): C = S @ (Wh + Wl)^T + bias. S exact fp16.
// Block 128x128, BK=32, 8 warps (32x64 warp tile), 3-stage cp.async.
// ---------------------------------------------------------------------------
__global__ __launch_bounds__(256)
void gemm_mma2(const __half* __restrict__ Ahalf,
               const __half* __restrict__ Bh, const __half* __restrict__ Bl,
               const float* __restrict__ bias, float* __restrict__ C)
{
    constexpr int BK = 32;
    constexpr int STAGES = 3;
    constexpr int LDA = BK + 8;              // 40 halves
    constexpr int TILEH = 128 * LDA;
    constexpr int KCH = KK / BK;             // 16
    constexpr int NCH = 2 * KCH;             // 2 terms

    extern __shared__ __half smem[];
    __half* sA = smem;
    __half* sB = smem + STAGES * TILEH;

    const int tid  = threadIdx.x;
    const int lane = tid & 31;
    const int wid  = tid >> 5;
    const int wm   = wid & 3;
    const int wn   = wid >> 2;

    const int rowBase = blockIdx.y * 128;
    const int colBase = blockIdx.x * 128;

    const __half* Abase = Ahalf + (size_t)rowBase * KK;
    const __half* Bsrc[2] = { Bh + (size_t)colBase * KK, Bl + (size_t)colBase * KK };

    const int q0r = tid >> 2, q0c = tid & 3;
    const int q1r = (tid + 256) >> 2;

    auto issue = [&](int ch, int stage) {
        const int term = ch / KCH;
        const int kofs = (ch % KCH) * BK;
        const __half* Bb = Bsrc[term];
        __half* dA = sA + stage * TILEH;
        __half* dB = sB + stage * TILEH;
        cp16(smem_u32(dA + q0r * LDA + q0c * 8), Abase + (size_t)q0r * KK + kofs + q0c * 8);
        cp16(smem_u32(dA + q1r * LDA + q0c * 8), Abase + (size_t)q1r * KK + kofs + q0c * 8);
        cp16(smem_u32(dB + q0r * LDA + q0c * 8), Bb + (size_t)q0r * KK + kofs + q0c * 8);
        cp16(smem_u32(dB + q1r * LDA + q0c * 8), Bb + (size_t)q1r * KK + kofs + q0c * 8);
        asm volatile("cp.async.commit_group;");
    };

    float acc[2][8][4];
#pragma unroll
    for (int i = 0; i < 2; i++)
#pragma unroll
        for (int j = 0; j < 8; j++)
#pragma unroll
            for (int k = 0; k < 4; k++) acc[i][j][k] = 0.0f;

    issue(0, 0);
    issue(1, 1);

    for (int ch = 0; ch < NCH; ch++) {
        asm volatile("cp.async.wait_group 1;");
        __syncthreads();

        if (ch + 2 < NCH) issue(ch + 2, (ch + 2) % STAGES);
        else              asm volatile("cp.async.commit_group;");

        const __half* a_s = sA + (ch % STAGES) * TILEH;
        const __half* b_s = sB + (ch % STAGES) * TILEH;

#pragma unroll
        for (int ks = 0; ks < 2; ks++) {
            uint32_t afrag[2][4], bfrag[4][4];
            const int colh = ks * 16 + ((lane >> 4) << 3);
#pragma unroll
            for (int i = 0; i < 2; i++) {
                const int row = wm * 32 + i * 16 + (lane & 15);
                ldsm_x4(afrag[i], smem_u32(a_s + row * LDA + colh));
            }
#pragma unroll
            for (int j = 0; j < 4; j++) {
                const int row = wn * 64 + j * 16 + (lane & 15);
                ldsm_x4(bfrag[j], smem_u32(b_s + row * LDA + colh));
            }
#pragma unroll
            for (int i = 0; i < 2; i++)
#pragma unroll
                for (int j = 0; j < 8; j++)
                    mma16816(acc[i][j], afrag[i],
                             bfrag[j >> 1][j & 1], bfrag[j >> 1][2 + (j & 1)]);
        }
    }

#pragma unroll
    for (int i = 0; i < 2; i++) {
        const int r0 = rowBase + wm * 32 + i * 16 + (lane >> 2);
#pragma unroll
        for (int j = 0; j < 8; j++) {
            const int c0 = colBase + wn * 64 + j * 8 + (lane & 3) * 2;
            const float b0 = __ldg(bias + c0);
            const float b1 = __ldg(bias + c0 + 1);
            float2 v0 = {acc[i][j][0] + b0, acc[i][j][1] + b1};
            float2 v1 = {acc[i][j][2] + b0, acc[i][j][3] + b1};
            *(float2*)(C + (size_t)r0 * NN + c0)       = v0;
            *(float2*)(C + (size_t)(r0 + 8) * NN + c0) = v1;
        }
    }
}

// ---------------------------------------------------------------------------
// Multistep LIF: h fp32 -> spikes fp16 (exact 0/1)
// ---------------------------------------------------------------------------
__global__ __launch_bounds__(256) void lif_scan(
    const float* __restrict__ h, __half* __restrict__ s)
{
    const int idx2 = blockIdx.x * blockDim.x + threadIdx.x;
    const size_t stride2 = (size_t)BB * NN / 2;
    const float2* hp = (const float2*)h;
    __half2* sp = (__half2*)s;
    float vx = 0.0f, vy = 0.0f;
    const __half one = __float2half(1.0f);
    const __half zero = __float2half(0.0f);
#pragma unroll 4
    for (int t = 0; t < TT; t++) {
        float2 ht = hp[(size_t)t * stride2 + idx2];
        vx += (ht.x - vx) * 0.5f;
        vy += (ht.y - vy) * 0.5f;
        const bool f0 = (vx >= 1.0f);
        const bool f1 = (vy >= 1.0f);
        sp[(size_t)t * stride2 + idx2] = __halves2half2(f0 ? one : zero, f1 ? one : zero);
        if (f0) vx = 0.0f;
        if (f1) vy = 0.0f;
    }
}

// ---------------------------------------------------------------------------
// kernel_launch: fc1 fp32 (flip-exact) -> LIF -> fc2 fp16 MMA (continuous)
// ---------------------------------------------------------------------------
extern "C" void kernel_launch(void* const* d_in, const int* in_sizes, int n_in,
                              void* d_out, int out_size)
{
    const float* x     = (const float*)d_in[0];
    const float* fc1_w = (const float*)d_in[1];
    const float* fc1_b = (const float*)d_in[2];
    const float* fc2_w = (const float*)d_in[3];
    const float* fc2_b = (const float*)d_in[4];
    float* out = (float*)d_out;

    float* h; __half *s, *w2h, *w2l;
    cudaGetSymbolAddress((void**)&h, g_h);
    cudaGetSymbolAddress((void**)&s, g_s);
    cudaGetSymbolAddress((void**)&w2h, g_w2h);
    cudaGetSymbolAddress((void**)&w2l, g_w2l);

    const int SMEM = 3 * 2 * 128 * 40 * (int)sizeof(__half);  // 61,440 B
    cudaFuncSetAttribute(gemm_mma2, cudaFuncAttributeMaxDynamicSharedMemorySize, SMEM);

    // Split W2 into fp16 hi/lo
    {
        int w4 = (NN * KK) / 4;
        split_f32_f16<<<w4 / 256, 256>>>(fc2_w, w2h, w2l, w4);
    }

    dim3 block(256);
    dim3 grid(NN / 128, M_TOTAL / 128);  // (4, 512)

    // fc1: fp32 (threshold-exact)
    gemm_f32<<<grid, block>>>(x, fc1_w, fc1_b, h, M_TOTAL, NN, KK);

    // LIF scan -> fp16 spikes
    lif_scan<<<(BB * NN / 2) / 256, 256>>>(h, s);

    // fc2: fp16 MMA, 2-term weight split (continuous output, no threshold)
    gemm_mma2<<<grid, block, SMEM>>>(s, w2h, w2l, fc2_b, out);
}

// round 14
// speedup vs baseline: 2.1163x; 1.4461x over previous
#include <cuda_runtime.h>
#include <cuda_fp16.h>
#include <cstdint>

// Problem dims (fixed)
#define TT 64
#define BB 1024
#define NN 512
#define KK 512
#define M_TOTAL (TT * BB)   // 65536
#define CAP 65536
#define EPS 3e-4f           // flag margin (approx-h error tail ~1e-5 -> 30x slack)

// Scratch (no allocs allowed)
__device__ __half g_ah[(size_t)M_TOTAL * KK];
__device__ __half g_al[(size_t)M_TOTAL * KK];
__device__ float  g_h [(size_t)M_TOTAL * NN];
__device__ __half g_s [(size_t)M_TOTAL * NN];
__device__ __half g_w1h[NN * KK];
__device__ __half g_w1l[NN * KK];
__device__ __half g_w2h[NN * KK];
__device__ int    g_cnt;
__device__ int    g_list[CAP];

// ---------------------------------------------------------------------------
// Helpers (sm_80-baseline PTX)
// ---------------------------------------------------------------------------
__device__ __forceinline__ uint32_t smem_u32(const void* p) {
    uint32_t a;
    asm("{ .reg .u64 t; cvta.to.shared.u64 t, %1; cvt.u32.u64 %0, t; }"
        : "=r"(a) : "l"(p));
    return a;
}
__device__ __forceinline__ void cp16(uint32_t saddr, const void* g) {
    asm volatile("cp.async.cg.shared.global [%0], [%1], 16;" :: "r"(saddr), "l"(g));
}
__device__ __forceinline__ void ldsm_x4(uint32_t* r, uint32_t a) {
    asm volatile("ldmatrix.sync.aligned.m8n8.x4.shared.b16 {%0,%1,%2,%3}, [%4];"
                 : "=r"(r[0]), "=r"(r[1]), "=r"(r[2]), "=r"(r[3]) : "r"(a));
}
__device__ __forceinline__ void mma16816(float* d, const uint32_t* a,
                                         uint32_t b0, uint32_t b1) {
    asm volatile(
        "mma.sync.aligned.m16n8k16.row.col.f32.f16.f16.f32 "
        "{%0,%1,%2,%3}, {%4,%5,%6,%7}, {%8,%9}, {%0,%1,%2,%3};"
        : "+f"(d[0]), "+f"(d[1]), "+f"(d[2]), "+f"(d[3])
        : "r"(a[0]), "r"(a[1]), "r"(a[2]), "r"(a[3]), "r"(b0), "r"(b1));
}

// ---------------------------------------------------------------------------
// Split fp32 -> fp16 hi + lo
// ---------------------------------------------------------------------------
__global__ __launch_bounds__(256) void split_f32_f16(
    const float* __restrict__ x, __half* __restrict__ h, __half* __restrict__ l,
    int n4)
{
    int i = blockIdx.x * blockDim.x + threadIdx.x;
    if (i >= n4) return;
    float4 v = ((const float4*)x)[i];
    float f[4] = {v.x, v.y, v.z, v.w};
    __half hh[4], ll[4];
#pragma unroll
    for (int j = 0; j < 4; j++) {
        hh[j] = __float2half_rn(f[j]);
        ll[j] = __float2half_rn(f[j] - __half2float(hh[j]));
    }
    ((__half2*)h)[2 * i]     = __halves2half2(hh[0], hh[1]);
    ((__half2*)h)[2 * i + 1] = __halves2half2(hh[2], hh[3]);
    ((__half2*)l)[2 * i]     = __halves2half2(ll[0], ll[1]);
    ((__half2*)l)[2 * i + 1] = __halves2half2(ll[2], ll[3]);
}

// fp32 -> fp16 (hi only, for W2 1-term)
__global__ __launch_bounds__(256) void cvt_f32_f16(
    const float* __restrict__ x, __half* __restrict__ h, int n4)
{
    int i = blockIdx.x * blockDim.x + threadIdx.x;
    if (i >= n4) return;
    float4 v = ((const float4*)x)[i];
    ((__half2*)h)[2 * i]     = __halves2half2(__float2half_rn(v.x), __float2half_rn(v.y));
    ((__half2*)h)[2 * i + 1] = __halves2half2(__float2half_rn(v.z), __float2half_rn(v.w));
}

__global__ void zero_cnt() { if (threadIdx.x == 0) g_cnt = 0; }

// ---------------------------------------------------------------------------
// mma.sync GEMM: C = sum_terms(A_t @ B_t^T) + bias
// NTERMS==3: AhBh + AhBl + AlBh (fc1 approx) ; NTERMS==1: AhBh (fc2)
// Block 128x128, BK=32, 8 warps, 3-stage cp.async. (R9-validated machinery.)
// ---------------------------------------------------------------------------
template <int NTERMS>
__global__ __launch_bounds__(256)
void gemm_mma(const __half* __restrict__ Ah, const __half* __restrict__ Al,
              const __half* __restrict__ Bh, const __half* __restrict__ Bl,
              const float* __restrict__ bias, float* __restrict__ C)
{
    constexpr int BK = 32;
    constexpr int STAGES = 3;
    constexpr int LDA = BK + 8;
    constexpr int TILEH = 128 * LDA;
    constexpr int KCH = KK / BK;          // 16
    constexpr int NCH = NTERMS * KCH;

    extern __shared__ __half smem[];
    __half* sA = smem;
    __half* sB = smem + STAGES * TILEH;

    const int tid  = threadIdx.x;
    const int lane = tid & 31;
    const int wid  = tid >> 5;
    const int wm   = wid & 3;
    const int wn   = wid >> 2;

    const int rowBase = blockIdx.y * 128;
    const int colBase = blockIdx.x * 128;

    const __half* Asrc[3];
    const __half* Bsrc[3];
    Asrc[0] = Ah + (size_t)rowBase * KK;  Bsrc[0] = Bh + (size_t)colBase * KK;
    Asrc[1] = Asrc[0];                    Bsrc[1] = Bl + (size_t)colBase * KK;
    Asrc[2] = (NTERMS == 3) ? (Al + (size_t)rowBase * KK) : Asrc[0];
    Bsrc[2] = Bsrc[0];

    const int q0r = tid >> 2, q0c = tid & 3;
    const int q1r = (tid + 256) >> 2;

    auto issue = [&](int ch, int stage) {
        const int term = ch / KCH;
        const int kofs = (ch % KCH) * BK;
        const __half* Ab = Asrc[term];
        const __half* Bb = Bsrc[term];
        __half* dA = sA + stage * TILEH;
        __half* dB = sB + stage * TILEH;
        cp16(smem_u32(dA + q0r * LDA + q0c * 8), Ab + (size_t)q0r * KK + kofs + q0c * 8);
        cp16(smem_u32(dA + q1r * LDA + q0c * 8), Ab + (size_t)q1r * KK + kofs + q0c * 8);
        cp16(smem_u32(dB + q0r * LDA + q0c * 8), Bb + (size_t)q0r * KK + kofs + q0c * 8);
        cp16(smem_u32(dB + q1r * LDA + q0c * 8), Bb + (size_t)q1r * KK + kofs + q0c * 8);
        asm volatile("cp.async.commit_group;");
    };

    float acc[2][8][4];
#pragma unroll
    for (int i = 0; i < 2; i++)
#pragma unroll
        for (int j = 0; j < 8; j++)
#pragma unroll
            for (int k = 0; k < 4; k++) acc[i][j][k] = 0.0f;

    issue(0, 0);
    if (NCH > 1) issue(1, 1);

    for (int ch = 0; ch < NCH; ch++) {
        asm volatile("cp.async.wait_group 1;");
        __syncthreads();

        if (ch + 2 < NCH) issue(ch + 2, (ch + 2) % STAGES);
        else              asm volatile("cp.async.commit_group;");

        const __half* a_s = sA + (ch % STAGES) * TILEH;
        const __half* b_s = sB + (ch % STAGES) * TILEH;

#pragma unroll
        for (int ks = 0; ks < 2; ks++) {
            uint32_t afrag[2][4], bfrag[4][4];
            const int colh = ks * 16 + ((lane >> 4) << 3);
#pragma unroll
            for (int i = 0; i < 2; i++) {
                const int row = wm * 32 + i * 16 + (lane & 15);
                ldsm_x4(afrag[i], smem_u32(a_s + row * LDA + colh));
            }
#pragma unroll
            for (int j = 0; j < 4; j++) {
                const int row = wn * 64 + j * 16 + (lane & 15);
                ldsm_x4(bfrag[j], smem_u32(b_s + row * LDA + colh));
            }
#pragma unroll
            for (int i = 0; i < 2; i++)
#pragma unroll
                for (int j = 0; j < 8; j++)
                    mma16816(acc[i][j], afrag[i],
                             bfrag[j >> 1][j & 1], bfrag[j >> 1][2 + (j & 1)]);
        }
    }

#pragma unroll
    for (int i = 0; i < 2; i++) {
        const int r0 = rowBase + wm * 32 + i * 16 + (lane >> 2);
#pragma unroll
        for (int j = 0; j < 8; j++) {
            const int c0 = colBase + wn * 64 + j * 8 + (lane & 3) * 2;
            const float b0 = __ldg(bias + c0);
            const float b1 = __ldg(bias + c0 + 1);
            float2 v0 = {acc[i][j][0] + b0, acc[i][j][1] + b1};
            float2 v1 = {acc[i][j][2] + b0, acc[i][j][3] + b1};
            *(float2*)(C + (size_t)r0 * NN + c0)       = v0;
            *(float2*)(C + (size_t)(r0 + 8) * NN + c0) = v1;
        }
    }
}

// ---------------------------------------------------------------------------
// LIF scan with near-threshold flagging. 2 neurons/thread.
// ---------------------------------------------------------------------------
__global__ __launch_bounds__(256) void lif_scan_flag(
    const float* __restrict__ h, __half* __restrict__ s)
{
    const int idx2 = blockIdx.x * blockDim.x + threadIdx.x;
    const size_t stride2 = (size_t)BB * NN / 2;
    const float2* hp = (const float2*)h;
    __half2* sp = (__half2*)s;
    float vx = 0.0f, vy = 0.0f;
    bool fl0 = false, fl1 = false;
    const __half one = __float2half(1.0f);
    const __half zero = __float2half(0.0f);
#pragma unroll 4
    for (int t = 0; t < TT; t++) {
        float2 ht = hp[(size_t)t * stride2 + idx2];
        vx += (ht.x - vx) * 0.5f;
        vy += (ht.y - vy) * 0.5f;
        fl0 |= (fabsf(vx - 1.0f) < EPS);
        fl1 |= (fabsf(vy - 1.0f) < EPS);
        const bool f0 = (vx >= 1.0f);
        const bool f1 = (vy >= 1.0f);
        sp[(size_t)t * stride2 + idx2] = __halves2half2(f0 ? one : zero, f1 ? one : zero);
        if (f0) vx = 0.0f;
        if (f1) vy = 0.0f;
    }
    if (fl0) { int p = atomicAdd(&g_cnt, 1); if (p < CAP) g_list[p] = 2 * idx2; }
    if (fl1) { int p = atomicAdd(&g_cnt, 1); if (p < CAP) g_list[p] = 2 * idx2 + 1; }
}

// ---------------------------------------------------------------------------
// Fixup (SEQUENTIAL ORDER): one thread per timestep does a pure sequential-k
// fmaf dot — bit-identical op sequence to the R1 fp32 GEMM, which measured
// ZERO spike flips vs the reference. Bias added once at the end (as R1 does).
// ---------------------------------------------------------------------------
__global__ __launch_bounds__(64) void fixup_seq(
    const float* __restrict__ x, const float* __restrict__ w1,
    const float* __restrict__ b1, __half* __restrict__ s)
{
    int cnt = g_cnt; if (cnt > CAP) cnt = CAP;
    const int i = blockIdx.x;
    if (i >= cnt) return;
    const int e = g_list[i];
    const int b = e / NN, n = e % NN;

    __shared__ float sh[TT];
    const int t = threadIdx.x;                      // 0..63, one t per thread
    const float4* xr = (const float4*)(x + ((size_t)t * BB + b) * KK);
    const float4* wr = (const float4*)(w1 + (size_t)n * KK);

    float acc = 0.0f;
    for (int k4 = 0; k4 < KK / 4; k4++) {           // strictly ascending k
        float4 xv = xr[k4];
        float4 wv = wr[k4];
        acc = fmaf(xv.x, wv.x, acc);
        acc = fmaf(xv.y, wv.y, acc);
        acc = fmaf(xv.z, wv.z, acc);
        acc = fmaf(xv.w, wv.w, acc);
    }
    sh[t] = acc + __ldg(b1 + n);                    // plain add at end, like R1
    __syncthreads();

    if (t == 0) {
        float v = 0.0f;
        const __half one = __float2half(1.0f);
        const __half zero = __float2half(0.0f);
        for (int tt = 0; tt < TT; tt++) {
            v += (sh[tt] - v) * 0.5f;
            const bool f = (v >= 1.0f);
            s[((size_t)tt * BB + b) * NN + n] = f ? one : zero;
            if (f) v = 0.0f;
        }
    }
}

// ---------------------------------------------------------------------------
// kernel_launch
// ---------------------------------------------------------------------------
extern "C" void kernel_launch(void* const* d_in, const int* in_sizes, int n_in,
                              void* d_out, int out_size)
{
    const float* x     = (const float*)d_in[0];
    const float* fc1_w = (const float*)d_in[1];
    const float* fc1_b = (const float*)d_in[2];
    const float* fc2_w = (const float*)d_in[3];
    const float* fc2_b = (const float*)d_in[4];
    float* out = (float*)d_out;

    __half *ah, *al, *s, *w1h, *w1l, *w2h;
    float* h;
    cudaGetSymbolAddress((void**)&ah, g_ah);
    cudaGetSymbolAddress((void**)&al, g_al);
    cudaGetSymbolAddress((void**)&h, g_h);
    cudaGetSymbolAddress((void**)&s, g_s);
    cudaGetSymbolAddress((void**)&w1h, g_w1h);
    cudaGetSymbolAddress((void**)&w1l, g_w1l);
    cudaGetSymbolAddress((void**)&w2h, g_w2h);

    const int SMEM = 3 * 2 * 128 * 40 * (int)sizeof(__half);  // 61,440 B
    cudaFuncSetAttribute(gemm_mma<3>, cudaFuncAttributeMaxDynamicSharedMemorySize, SMEM);
    cudaFuncSetAttribute(gemm_mma<1>, cudaFuncAttributeMaxDynamicSharedMemorySize, SMEM);

    // Splits: x -> hi/lo ; W1 -> hi/lo ; W2 -> hi only (1-term fc2)
    {
        int n4 = (M_TOTAL * KK) / 4;
        split_f32_f16<<<n4 / 256, 256>>>(x, ah, al, n4);
        int w4 = (NN * KK) / 4;
        split_f32_f16<<<w4 / 256, 256>>>(fc1_w, w1h, w1l, w4);
        cvt_f32_f16<<<w4 / 256, 256>>>(fc2_w, w2h, w4);
    }
    zero_cnt<<<1, 32>>>();

    dim3 block(256);
    dim3 grid(NN / 128, M_TOTAL / 128);  // (4, 512)

    // fc1: 3-term fp16 MMA (approximate h)
    gemm_mma<3><<<grid, block, SMEM>>>(ah, al, w1h, w1l, fc1_b, h);

    // LIF scan + flag near-threshold neurons
    lif_scan_flag<<<(BB * NN / 2) / 256, 256>>>(h, s);

    // Sequential-order fp32 recompute of flagged neurons (R1-exact arithmetic)
    fixup_seq<<<CAP, 64>>>(x, fc1_w, fc1_b, s);

    // fc2: 1-term fp16 MMA (spikes exact; W2 rounding -> out err ~1.4e-4)
    gemm_mma<1><<<grid, block, SMEM>>>(s, nullptr, w2h, w2h, fc2_b, out);
}